// round 12
// baseline (speedup 1.0000x reference)
#include <cuda_runtime.h>
#include <cuda_fp16.h>
#include <cstdint>
#include <cstddef>

// ---------------------------------------------------------------------------
// Problem dims
// ---------------------------------------------------------------------------
#define BATCH 4096
#define FEAT  2048

// GEMM tiling: CTA 128x128, 4 warps of 64x64, BK=64, 3-stage pipeline
#define BM 128
#define BN 128
#define BK 64
#define NCHUNK (FEAT / BK)     // 32
#define STG 3

// Merged-grid tile layout (topological bid order):
//  [0,64):      W0 convert tiles
//  [64,192):    sigmoid tiles (32 rows each)
//  [192,+576)x3: layers 0-2 blocks = 512 GEMM (bx-major) + 64 next-W cvt, 8:1
//  then 512 layer-3 GEMM tiles, then 128 head tiles. total 2560.
#define NCVT0  64
#define NSIG   128
#define T_PREP (NCVT0 + NSIG)          // 192
#define LBLK   576
#define T_L3   (T_PREP + 3 * LBLK)     // 1920
#define T_HEAD (T_L3 + 512)            // 2432
#define TOTALT (T_HEAD + 128)          // 2560

// Shared memory: row = 64 halfs = 128B = 8 x 16B units.
#define ASTG (BM * 128)                // 16384 B per stage
#define BSTG (BN * 128)                // 16384 B per stage
#define SM_A 0
#define SM_B (STG * ASTG)              // 49152
#define SMEM_BYTES (SM_B + STG * BSTG) // 98304

// ---------------------------------------------------------------------------
// Device scratch + scheduling state (allocation-free rule: __device__ globals)
// ---------------------------------------------------------------------------
__device__ __align__(16) __half g_w[4][(size_t)FEAT * FEAT];     // 64 MB fp16 weights
__device__ __align__(16) __half g_act[2][(size_t)BATCH * FEAT];  // 32 MB activations
__device__ int g_gdone[4][32];   // per (layer, bx) completed column-tiles (target 16)
__device__ int g_cdone[3];       // per converted weight W1..W3 (target 64)
__device__ int g_cdone0;         // W0 convert tiles done (target 64)
__device__ int g_sdone[32];      // sigmoid sub-tiles done per bx block (target 4)

// ---------------------------------------------------------------------------
// PTX helpers (plain compute_80-level PTX: legal on compute_103)
// ---------------------------------------------------------------------------
__device__ __forceinline__ uint32_t smem_u32(const void* p) {
    uint32_t a;
    asm("{ .reg .u64 t; cvta.to.shared.u64 t, %1; cvt.u32.u64 %0, t; }"
        : "=r"(a) : "l"(p));
    return a;
}

__device__ __forceinline__ void cp_async16(uint32_t dst, const void* src) {
    asm volatile("cp.async.cg.shared.global [%0], [%1], 16;"
                 :: "r"(dst), "l"(src));
}
#define CP_COMMIT() asm volatile("cp.async.commit_group;" ::: "memory")
#define CP_WAIT(n)  asm volatile("cp.async.wait_group %0;" :: "n"(n) : "memory")

__device__ __forceinline__ void ldm_x4(uint32_t* r, uint32_t addr) {
    asm volatile("ldmatrix.sync.aligned.m8n8.x4.shared.b16 {%0,%1,%2,%3}, [%4];"
                 : "=r"(r[0]), "=r"(r[1]), "=r"(r[2]), "=r"(r[3]) : "r"(addr));
}

__device__ __forceinline__ void mma16816(float* c, const uint32_t* a, const uint32_t* b) {
    asm volatile(
        "mma.sync.aligned.m16n8k16.row.col.f32.f16.f16.f32 "
        "{%0,%1,%2,%3}, {%4,%5,%6,%7}, {%8,%9}, {%0,%1,%2,%3};"
        : "+f"(c[0]), "+f"(c[1]), "+f"(c[2]), "+f"(c[3])
        : "r"(a[0]), "r"(a[1]), "r"(a[2]), "r"(a[3]), "r"(b[0]), "r"(b[1]));
}

// L2-coherent vector load (L1 bypass) for data written earlier in this kernel
__device__ __forceinline__ uint4 ldg_cg_v4(const void* p) {
    uint4 v;
    asm volatile("ld.global.cg.v4.u32 {%0,%1,%2,%3}, [%4];"
                 : "=r"(v.x), "=r"(v.y), "=r"(v.z), "=r"(v.w) : "l"(p));
    return v;
}

// Swizzle for 128B rows (8 x 16B units): phys unit = u ^ (row & 7).
__device__ __forceinline__ uint32_t sw_off(int row, int u) {
    return (uint32_t)(row * 128 + ((u ^ (row & 7)) << 4));
}

// ---------------------------------------------------------------------------
// Scheduler-state reset (graph-replay safe: runs every invocation)
// ---------------------------------------------------------------------------
__global__ void init_kernel()
{
    const int t = threadIdx.x;
    if (t < 32) {
        #pragma unroll
        for (int l = 0; l < 4; l++) g_gdone[l][t] = 0;
        g_sdone[t] = 0;
    }
    if (t < 3) g_cdone[t] = 0;
    if (t == 0) g_cdone0 = 0;
}

// ---------------------------------------------------------------------------
// Merged network kernel: prep + 4 GEMM layers + head; one tile per CTA,
// HW-scheduled in topological bid order, dep-gated by done-counters.
// ---------------------------------------------------------------------------
__global__ void __launch_bounds__(128, 2)
fused_net_kernel(const float* __restrict__ x,
                 const float* __restrict__ cw, const float* __restrict__ cb,
                 const float* __restrict__ W0f, const float* __restrict__ W1f,
                 const float* __restrict__ W2f, const float* __restrict__ W3f,
                 const float* __restrict__ b0, const float* __restrict__ b1,
                 const float* __restrict__ b2, const float* __restrict__ b3,
                 const float* __restrict__ Wh, const float* __restrict__ bh,
                 float* __restrict__ outp)
{
    extern __shared__ char smem[];
    const uint32_t sb = smem_u32(smem);

    const int tid  = threadIdx.x;
    const int lane = tid & 31;
    const int wid  = tid >> 5;
    const int id   = blockIdx.x;

    // ================= prep tiles =================
    if (id < NCVT0) {
        // W0 converter tile
        const int per = (FEAT * FEAT / 4) / 64;            // 16384 float4
        const float4* s4 = (const float4*)W0f + (size_t)id * per;
        uint2* d4 = (uint2*)g_w[0] + (size_t)id * per;
        #pragma unroll 4
        for (int i = tid; i < per; i += 128) {
            float4 v = s4[i];
            __half2 h0 = __floats2half2_rn(v.x, v.y);
            __half2 h1 = __floats2half2_rn(v.z, v.w);
            d4[i] = make_uint2(*reinterpret_cast<uint32_t*>(&h0),
                               *reinterpret_cast<uint32_t*>(&h1));
        }
        __threadfence();
        __syncthreads();
        if (tid == 0) atomicAdd(&g_cdone0, 1);
        return;
    }
    if (id < T_PREP) {
        // sigmoid tile: 32 rows of x -> fp16 activations
        const int t = id - NCVT0;                          // 0..127
        const int per = 16384;                             // 32*2048/4 float4
        const float s = cw[0] + cw[1] + cw[2] + cw[3];
        const float c = cb[0];
        const float4* x4 = (const float4*)x + (size_t)t * per;
        uint2* o4 = (uint2*)g_act[0] + (size_t)t * per;
        #pragma unroll 4
        for (int i = tid; i < per; i += 128) {
            float4 v = x4[i];
            float a0 = 1.0f / (1.0f + __expf(-(v.x * s + c)));
            float a1 = 1.0f / (1.0f + __expf(-(v.y * s + c)));
            float a2 = 1.0f / (1.0f + __expf(-(v.z * s + c)));
            float a3 = 1.0f / (1.0f + __expf(-(v.w * s + c)));
            __half2 h0 = __floats2half2_rn(a0, a1);
            __half2 h1 = __floats2half2_rn(a2, a3);
            o4[i] = make_uint2(*reinterpret_cast<uint32_t*>(&h0),
                               *reinterpret_cast<uint32_t*>(&h1));
        }
        __threadfence();
        __syncthreads();
        if (tid == 0) atomicAdd(&g_sdone[t >> 2], 1);
        return;
    }

    // -------- decode post-prep tile --------
    int layer, g = -1, cvt = -1;
    if (id < T_L3) {
        const int rel = id - T_PREP;
        layer = rel / LBLK;
        const int pos = rel - layer * LBLK;
        const int grp = pos / 9, r = pos - grp * 9;
        if (r == 8) cvt = grp;              // convert W(layer+1), sub-tile grp
        else        g   = grp * 8 + r;      // GEMM tile, bx-major
    } else if (id < T_HEAD) {
        layer = 3;
        g = id - T_L3;
    } else {
        layer = 4;                          // head
    }

    if (cvt >= 0) {
        // ================= weight converter tile (W1..W3) =================
        const float* src = (layer == 0) ? W1f : (layer == 1) ? W2f : W3f;
        const int per = (FEAT * FEAT / 4) / 64;            // 16384 float4
        const float4* s4 = (const float4*)src + (size_t)cvt * per;
        uint2* d4 = (uint2*)g_w[layer + 1] + (size_t)cvt * per;
        #pragma unroll 4
        for (int i = tid; i < per; i += 128) {
            float4 v = s4[i];
            __half2 h0 = __floats2half2_rn(v.x, v.y);
            __half2 h1 = __floats2half2_rn(v.z, v.w);
            d4[i] = make_uint2(*reinterpret_cast<uint32_t*>(&h0),
                               *reinterpret_cast<uint32_t*>(&h1));
        }
        __threadfence();
        __syncthreads();
        if (tid == 0) atomicAdd(&g_cdone[layer], 1);
        return;
    }

    if (layer == 4) {
        // ================= head tile: 32 rows =================
        const int hx = id - T_HEAD;                 // 0..127
        const int bx = hx >> 2;
        if (tid == 0)
            while (*(volatile int*)&g_gdone[3][bx] < 16) __nanosleep(64);
        __syncthreads();

        const __half* h = g_act[0];
        const float4* wh0 = (const float4*)Wh + lane * 16;          // 64 floats
        const float4* wh1 = (const float4*)(Wh + FEAT) + lane * 16;
        const float bh0 = bh[0], bh1 = bh[1];

        #pragma unroll 1
        for (int rr = 0; rr < 8; rr++) {
            const int r = hx * 32 + wid * 8 + rr;
            const char* hrow = (const char*)(h + (size_t)r * FEAT + lane * 64);
            float s0 = 0.0f, s1 = 0.0f;
            #pragma unroll
            for (int q = 0; q < 8; q++) {
                uint4 v = ldg_cg_v4(hrow + q * 16);   // 8 halfs
                float4 wa0 = wh0[2 * q], wa1 = wh0[2 * q + 1];
                float4 wb0 = wh1[2 * q], wb1 = wh1[2 * q + 1];
                const __half2* hp = (const __half2*)&v;
                float2 e0 = __half22float2(hp[0]);
                float2 e1 = __half22float2(hp[1]);
                float2 e2 = __half22float2(hp[2]);
                float2 e3 = __half22float2(hp[3]);
                s0 += e0.x * wa0.x + e0.y * wa0.y + e1.x * wa0.z + e1.y * wa0.w
                    + e2.x * wa1.x + e2.y * wa1.y + e3.x * wa1.z + e3.y * wa1.w;
                s1 += e0.x * wb0.x + e0.y * wb0.y + e1.x * wb0.z + e1.y * wb0.w
                    + e2.x * wb1.x + e2.y * wb1.y + e3.x * wb1.z + e3.y * wb1.w;
            }
            #pragma unroll
            for (int off = 16; off; off >>= 1) {
                s0 += __shfl_down_sync(0xFFFFFFFFu, s0, off);
                s1 += __shfl_down_sync(0xFFFFFFFFu, s1, off);
            }
            if (lane == 0) {
                outp[r * 2 + 0] = s0 + bh0;
                outp[r * 2 + 1] = s1 + bh1;
            }
        }
        return;
    }

    // ================= GEMM tile =================
    const int bx = g >> 4, by = g & 15;             // bx-major ordering
    const int m0 = bx * BM, n0 = by * BN;

    if (tid == 0) {
        if (layer == 0) {
            while (*(volatile int*)&g_sdone[bx] < 4) __nanosleep(64);
            while (*(volatile int*)&g_cdone0 < 64) __nanosleep(64);
        } else {
            while (*(volatile int*)&g_gdone[layer - 1][bx] < 16) __nanosleep(64);
            while (*(volatile int*)&g_cdone[layer - 1] < 64) __nanosleep(64);
        }
    }
    __syncthreads();

    const __half* A = g_act[layer & 1];
    const __half* W = g_w[layer];
    const float* bias = (layer == 0) ? b0 : (layer == 1) ? b1
                      : (layer == 2) ? b2 : b3;
    __half* outh = g_act[(layer + 1) & 1];

    const int wm = wid >> 1, wn = wid & 1;
    const int grp = lane >> 3;
    uint32_t pa[4], qa[4];
    #pragma unroll
    for (int t = 0; t < 4; t++) {
        int row = wm * 64 + t * 16 + (grp & 1) * 8 + (lane & 7);
        pa[t] = (uint32_t)(row * 128);
        qa[t] = (uint32_t)((grp >> 1) ^ (row & 7));
    }
    uint32_t pb[4], qb[4];
    #pragma unroll
    for (int p = 0; p < 4; p++) {
        int row = wn * 64 + p * 16 + (grp >> 1) * 8 + (lane & 7);
        pb[p] = (uint32_t)(row * 128);
        qb[p] = (uint32_t)((grp & 1) ^ (row & 7));
    }
    const int lrow = tid >> 3, lu = tid & 7;
    const __half* agp = A + (size_t)(m0 + lrow) * FEAT + lu * 8;
    const __half* bgp = W + (size_t)(n0 + lrow) * FEAT + lu * 8;

    auto load_chunk = [&](int ck, int s) {
        const int k0 = ck * BK;
        #pragma unroll
        for (int i = 0; i < 8; i++) {
            int row = lrow + i * 16;
            cp_async16(sb + SM_A + s * ASTG + sw_off(row, lu),
                       agp + (size_t)i * 16 * FEAT + k0);
        }
        #pragma unroll
        for (int i = 0; i < 8; i++) {
            int row = lrow + i * 16;
            cp_async16(sb + SM_B + s * BSTG + sw_off(row, lu),
                       bgp + (size_t)i * 16 * FEAT + k0);
        }
        CP_COMMIT();
    };

    uint32_t af[2][4][4], bf[2][8][2];
    auto preload = [&](int buf, uint32_t ab, uint32_t bb, uint32_t ux) {
        #pragma unroll
        for (int t = 0; t < 4; t++)
            ldm_x4(af[buf][t], ab + pa[t] + ((qa[t] ^ ux) << 4));
        #pragma unroll
        for (int p = 0; p < 4; p++) {
            uint32_t r[4];
            ldm_x4(r, bb + pb[p] + ((qb[p] ^ ux) << 4));
            bf[buf][2 * p][0] = r[0]; bf[buf][2 * p][1] = r[1];
            bf[buf][2 * p + 1][0] = r[2]; bf[buf][2 * p + 1][1] = r[3];
        }
    };

    float acc[4][8][4];
    #pragma unroll
    for (int t = 0; t < 4; t++)
        #pragma unroll
        for (int n = 0; n < 8; n++)
            #pragma unroll
            for (int e = 0; e < 4; e++) acc[t][n][e] = 0.0f;

    load_chunk(0, 0);
    load_chunk(1, 1);
    CP_WAIT(1);
    __syncthreads();
    preload(0, sb + SM_A, sb + SM_B, 0);

    int s = 0;
    for (int i = 0; i < NCHUNK; i++) {
        const uint32_t ab = sb + SM_A + s * ASTG;
        const uint32_t bb = sb + SM_B + s * BSTG;

        if (i + 2 < NCHUNK) {
            int ls = s + 2; if (ls >= STG) ls -= STG;
            load_chunk(i + 2, ls);
        }

        #pragma unroll
        for (int ks = 0; ks < 3; ks++) {
            const int cur = ks & 1;
            preload(cur ^ 1, ab, bb, (uint32_t)(2 * (ks + 1)));
            #pragma unroll
            for (int t = 0; t < 4; t++)
                #pragma unroll
                for (int n = 0; n < 8; n++)
                    mma16816(acc[t][n], af[cur][t], bf[cur][n]);
        }

        if (i + 1 < NCHUNK) {
            if (i + 2 < NCHUNK) CP_WAIT(1); else CP_WAIT(0);
            __syncthreads();
            int ns = s + 1; if (ns >= STG) ns -= STG;
            preload(0, sb + SM_A + ns * ASTG, sb + SM_B + ns * BSTG, 0);
        }
        #pragma unroll
        for (int t = 0; t < 4; t++)
            #pragma unroll
            for (int n = 0; n < 8; n++)
                mma16816(acc[t][n], af[1][t], bf[1][n]);

        if (++s == STG) s = 0;
    }

    // epilogue: bias + relu + fp16 store
    #pragma unroll
    for (int t = 0; t < 4; t++) {
        const int r0 = m0 + wm * 64 + t * 16 + (lane >> 2);
        #pragma unroll
        for (int n = 0; n < 8; n++) {
            const int col = n0 + wn * 64 + n * 8 + (lane & 3) * 2;
            const float2 bv = *reinterpret_cast<const float2*>(bias + col);
            float f0 = fmaxf(acc[t][n][0] + bv.x, 0.0f);
            float f1 = fmaxf(acc[t][n][1] + bv.y, 0.0f);
            float f2 = fmaxf(acc[t][n][2] + bv.x, 0.0f);
            float f3 = fmaxf(acc[t][n][3] + bv.y, 0.0f);
            *reinterpret_cast<__half2*>(outh + (size_t)r0 * FEAT + col) =
                __floats2half2_rn(f0, f1);
            *reinterpret_cast<__half2*>(outh + (size_t)(r0 + 8) * FEAT + col) =
                __floats2half2_rn(f2, f3);
        }
    }
    __threadfence();
    __syncthreads();
    if (tid == 0) atomicAdd(&g_gdone[layer][bx], 1);
}

// ---------------------------------------------------------------------------
// Launch
// ---------------------------------------------------------------------------
extern "C" void kernel_launch(void* const* d_in, const int* in_sizes, int n_in,
                              void* d_out, int out_size)
{
    const float* x  = (const float*)d_in[0];
    const float* cw = (const float*)d_in[1];
    const float* cb = (const float*)d_in[2];
    const float* Ws[4] = {(const float*)d_in[3], (const float*)d_in[5],
                          (const float*)d_in[7], (const float*)d_in[9]};
    const float* bs[4] = {(const float*)d_in[4], (const float*)d_in[6],
                          (const float*)d_in[8], (const float*)d_in[10]};
    const float* Wh = (const float*)d_in[11];
    const float* bh = (const float*)d_in[12];
    float* out = (float*)d_out;

    cudaFuncSetAttribute(fused_net_kernel,
                         cudaFuncAttributeMaxDynamicSharedMemorySize, SMEM_BYTES);

    init_kernel<<<1, 128>>>();
    fused_net_kernel<<<TOTALT, 128, SMEM_BYTES>>>(
        x, cw, cb, Ws[0], Ws[1], Ws[2], Ws[3],
        bs[0], bs[1], bs[2], bs[3], Wh, bh, out);
}

// round 14
// speedup vs baseline: 1.2861x; 1.2861x over previous
#include <cuda_runtime.h>
#include <cuda_fp16.h>
#include <cstdint>
#include <cstddef>

// ---------------------------------------------------------------------------
// Problem dims
// ---------------------------------------------------------------------------
#define BATCH 4096
#define FEAT  2048

// GEMM tiling: CTA 128x128, 4 warps of 64x64, BK=64, 3-stage pipeline
#define BM 128
#define BN 128
#define BK 64
#define NCHUNK (FEAT / BK)     // 32
#define STG 3

// Merged-grid tile layout (topological bid order):
//  layers 0-2: blocks of 576 = 512 GEMM tiles (bx-major) + 64 cvt tiles, 8:1.
//  layer 3:    512 GEMM tiles (epilogue emits head partials, no h store).
//  reduce:     32 tiles (one per bx) summing head partials.  total 2272.
#define LBLK   576
#define T_L3   (3 * LBLK)              // 1728
#define T_RED  (T_L3 + 512)            // 2240
#define TOTALT (T_RED + 32)            // 2272

// Shared memory: row = 64 halfs = 128B = 8 x 16B units.
#define ASTG (BM * 128)                // 16384 B per stage
#define BSTG (BN * 128)                // 16384 B per stage
#define SM_A 0
#define SM_B (STG * ASTG)              // 49152
#define SMEM_BYTES (SM_B + STG * BSTG) // 98304

// ---------------------------------------------------------------------------
// Device scratch + scheduling state (allocation-free rule: __device__ globals)
// ---------------------------------------------------------------------------
__device__ __align__(16) __half g_w[4][(size_t)FEAT * FEAT];     // 64 MB fp16 weights
__device__ __align__(16) __half g_act[2][(size_t)BATCH * FEAT];  // 32 MB activations
// head partials: 32 slots per row = (by, wn) pairs; 1 MB
__device__ __align__(16) float2 g_part[(size_t)BATCH * 32];
__device__ int g_gdone[4][32];   // per (layer, bx) completed column-tiles (target 16)
__device__ int g_cdone[3];       // per converted weight (target 64)

// ---------------------------------------------------------------------------
// PTX helpers (plain compute_80-level PTX: legal on compute_103)
// ---------------------------------------------------------------------------
__device__ __forceinline__ uint32_t smem_u32(const void* p) {
    uint32_t a;
    asm("{ .reg .u64 t; cvta.to.shared.u64 t, %1; cvt.u32.u64 %0, t; }"
        : "=r"(a) : "l"(p));
    return a;
}

__device__ __forceinline__ void cp_async16(uint32_t dst, const void* src) {
    asm volatile("cp.async.cg.shared.global [%0], [%1], 16;"
                 :: "r"(dst), "l"(src));
}
#define CP_COMMIT() asm volatile("cp.async.commit_group;" ::: "memory")
#define CP_WAIT(n)  asm volatile("cp.async.wait_group %0;" :: "n"(n) : "memory")

__device__ __forceinline__ void ldm_x4(uint32_t* r, uint32_t addr) {
    asm volatile("ldmatrix.sync.aligned.m8n8.x4.shared.b16 {%0,%1,%2,%3}, [%4];"
                 : "=r"(r[0]), "=r"(r[1]), "=r"(r[2]), "=r"(r[3]) : "r"(addr));
}

__device__ __forceinline__ void mma16816(float* c, const uint32_t* a, const uint32_t* b) {
    asm volatile(
        "mma.sync.aligned.m16n8k16.row.col.f32.f16.f16.f32 "
        "{%0,%1,%2,%3}, {%4,%5,%6,%7}, {%8,%9}, {%0,%1,%2,%3};"
        : "+f"(c[0]), "+f"(c[1]), "+f"(c[2]), "+f"(c[3])
        : "r"(a[0]), "r"(a[1]), "r"(a[2]), "r"(a[3]), "r"(b[0]), "r"(b[1]));
}

// L2-coherent vector load (L1 bypass) for data written earlier in this kernel
__device__ __forceinline__ uint4 ldg_cg_v4(const void* p) {
    uint4 v;
    asm volatile("ld.global.cg.v4.u32 {%0,%1,%2,%3}, [%4];"
                 : "=r"(v.x), "=r"(v.y), "=r"(v.z), "=r"(v.w) : "l"(p));
    return v;
}

// Swizzle for 128B rows (8 x 16B units): phys unit = u ^ (row & 7).
__device__ __forceinline__ uint32_t sw_off(int row, int u) {
    return (uint32_t)(row * 128 + ((u ^ (row & 7)) << 4));
}

// ---------------------------------------------------------------------------
// Merged network kernel: one tile per CTA, HW-scheduled, dep-gated by counters
// ---------------------------------------------------------------------------
__global__ void __launch_bounds__(128, 2)
fused_net_kernel(const float* __restrict__ b0, const float* __restrict__ b1,
                 const float* __restrict__ b2, const float* __restrict__ b3,
                 const float* __restrict__ W1f, const float* __restrict__ W2f,
                 const float* __restrict__ W3f,
                 const float* __restrict__ Wh, const float* __restrict__ bh,
                 float* __restrict__ outp)
{
    extern __shared__ char smem[];
    const uint32_t sb = smem_u32(smem);

    const int tid  = threadIdx.x;
    const int lane = tid & 31;
    const int wid  = tid >> 5;
    const int id   = blockIdx.x;

    // -------- decode tile --------
    int layer, g = -1, cvt = -1;
    if (id < T_L3) {
        layer = id / LBLK;
        const int pos = id - layer * LBLK;
        const int grp = pos / 9, r = pos - grp * 9;
        if (r == 8) cvt = grp;              // convert W(layer+1), sub-tile grp
        else        g   = grp * 8 + r;      // GEMM tile, bx-major
    } else if (id < T_RED) {
        layer = 3;
        g = id - T_L3;
    } else {
        layer = 4;                          // head reduce
    }

    if (cvt >= 0) {
        // ================= weight converter tile =================
        const float* src = (layer == 0) ? W1f : (layer == 1) ? W2f : W3f;
        const int per = (FEAT * FEAT / 4) / 64;            // 16384 float4
        const float4* s4 = (const float4*)src + (size_t)cvt * per;
        uint2* d4 = (uint2*)g_w[layer + 1] + (size_t)cvt * per;
        #pragma unroll 4
        for (int i = tid; i < per; i += 128) {
            float4 v = s4[i];
            __half2 h0 = __floats2half2_rn(v.x, v.y);
            __half2 h1 = __floats2half2_rn(v.z, v.w);
            d4[i] = make_uint2(*reinterpret_cast<uint32_t*>(&h0),
                               *reinterpret_cast<uint32_t*>(&h1));
        }
        __threadfence();
        __syncthreads();
        if (tid == 0) atomicAdd(&g_cdone[layer], 1);
        return;
    }

    if (layer == 4) {
        // ================= head reduce tile: 128 rows, fixed slot order =====
        const int bx = id - T_RED;                  // 0..31
        if (tid == 0)
            while (*(volatile int*)&g_gdone[3][bx] < 16) __nanosleep(64);
        __syncthreads();

        const int row = bx * 128 + tid;
        const char* base = (const char*)&g_part[(size_t)row * 32];  // 256B
        float s0 = bh[0], s1 = bh[1];
        #pragma unroll
        for (int q = 0; q < 16; q++) {              // 16 x 16B = 32 float2
            uint4 v = ldg_cg_v4(base + q * 16);
            s0 += __uint_as_float(v.x) + __uint_as_float(v.z);
            s1 += __uint_as_float(v.y) + __uint_as_float(v.w);
        }
        outp[row * 2 + 0] = s0;
        outp[row * 2 + 1] = s1;
        return;
    }

    // ================= GEMM tile =================
    const int bx = g >> 4, by = g & 15;             // bx-major ordering
    const int m0 = bx * BM, n0 = by * BN;

    if (tid == 0 && layer > 0) {
        while (*(volatile int*)&g_gdone[layer - 1][bx] < 16) __nanosleep(64);
        while (*(volatile int*)&g_cdone[layer - 1] < 64) __nanosleep(64);
    }
    __syncthreads();

    const __half* A = g_act[layer & 1];
    const __half* W = g_w[layer];
    const float* bias = (layer == 0) ? b0 : (layer == 1) ? b1
                      : (layer == 2) ? b2 : b3;
    __half* outh = g_act[(layer + 1) & 1];

    const int wm = wid >> 1, wn = wid & 1;
    const int grp = lane >> 3;
    uint32_t pa[4], qa[4];
    #pragma unroll
    for (int t = 0; t < 4; t++) {
        int row = wm * 64 + t * 16 + (grp & 1) * 8 + (lane & 7);
        pa[t] = (uint32_t)(row * 128);
        qa[t] = (uint32_t)((grp >> 1) ^ (row & 7));
    }
    uint32_t pb[4], qb[4];
    #pragma unroll
    for (int p = 0; p < 4; p++) {
        int row = wn * 64 + p * 16 + (grp >> 1) * 8 + (lane & 7);
        pb[p] = (uint32_t)(row * 128);
        qb[p] = (uint32_t)((grp & 1) ^ (row & 7));
    }
    const int lrow = tid >> 3, lu = tid & 7;
    const __half* agp = A + (size_t)(m0 + lrow) * FEAT + lu * 8;
    const __half* bgp = W + (size_t)(n0 + lrow) * FEAT + lu * 8;

    auto load_chunk = [&](int ck, int s) {
        const int k0 = ck * BK;
        #pragma unroll
        for (int i = 0; i < 8; i++) {
            int row = lrow + i * 16;
            cp_async16(sb + SM_A + s * ASTG + sw_off(row, lu),
                       agp + (size_t)i * 16 * FEAT + k0);
        }
        #pragma unroll
        for (int i = 0; i < 8; i++) {
            int row = lrow + i * 16;
            cp_async16(sb + SM_B + s * BSTG + sw_off(row, lu),
                       bgp + (size_t)i * 16 * FEAT + k0);
        }
        CP_COMMIT();
    };

    uint32_t af[2][4][4], bf[2][8][2];
    auto preload = [&](int buf, uint32_t ab, uint32_t bb, uint32_t ux) {
        #pragma unroll
        for (int t = 0; t < 4; t++)
            ldm_x4(af[buf][t], ab + pa[t] + ((qa[t] ^ ux) << 4));
        #pragma unroll
        for (int p = 0; p < 4; p++) {
            uint32_t r[4];
            ldm_x4(r, bb + pb[p] + ((qb[p] ^ ux) << 4));
            bf[buf][2 * p][0] = r[0]; bf[buf][2 * p][1] = r[1];
            bf[buf][2 * p + 1][0] = r[2]; bf[buf][2 * p + 1][1] = r[3];
        }
    };

    float acc[4][8][4];
    #pragma unroll
    for (int t = 0; t < 4; t++)
        #pragma unroll
        for (int n = 0; n < 8; n++)
            #pragma unroll
            for (int e = 0; e < 4; e++) acc[t][n][e] = 0.0f;

    load_chunk(0, 0);
    load_chunk(1, 1);
    CP_WAIT(1);
    __syncthreads();
    preload(0, sb + SM_A, sb + SM_B, 0);

    int s = 0;
    for (int i = 0; i < NCHUNK; i++) {
        const uint32_t ab = sb + SM_A + s * ASTG;
        const uint32_t bb = sb + SM_B + s * BSTG;

        if (i + 2 < NCHUNK) {
            int ls = s + 2; if (ls >= STG) ls -= STG;
            load_chunk(i + 2, ls);
        }

        #pragma unroll
        for (int ks = 0; ks < 3; ks++) {
            const int cur = ks & 1;
            preload(cur ^ 1, ab, bb, (uint32_t)(2 * (ks + 1)));
            #pragma unroll
            for (int t = 0; t < 4; t++)
                #pragma unroll
                for (int n = 0; n < 8; n++)
                    mma16816(acc[t][n], af[cur][t], bf[cur][n]);
        }

        if (i + 1 < NCHUNK) {
            if (i + 2 < NCHUNK) CP_WAIT(1); else CP_WAIT(0);
            __syncthreads();
            int ns = s + 1; if (ns >= STG) ns -= STG;
            preload(0, sb + SM_A + ns * ASTG, sb + SM_B + ns * BSTG, 0);
        }
        #pragma unroll
        for (int t = 0; t < 4; t++)
            #pragma unroll
            for (int n = 0; n < 8; n++)
                mma16816(acc[t][n], af[1][t], bf[1][n]);

        if (++s == STG) s = 0;
    }

    if (layer < 3) {
        // -------- epilogue: bias + relu + fp16 store --------
        #pragma unroll
        for (int t = 0; t < 4; t++) {
            const int r0 = m0 + wm * 64 + t * 16 + (lane >> 2);
            #pragma unroll
            for (int n = 0; n < 8; n++) {
                const int col = n0 + wn * 64 + n * 8 + (lane & 3) * 2;
                const float2 bv = *reinterpret_cast<const float2*>(bias + col);
                float f0 = fmaxf(acc[t][n][0] + bv.x, 0.0f);
                float f1 = fmaxf(acc[t][n][1] + bv.y, 0.0f);
                float f2 = fmaxf(acc[t][n][2] + bv.x, 0.0f);
                float f3 = fmaxf(acc[t][n][3] + bv.y, 0.0f);
                *reinterpret_cast<__half2*>(outh + (size_t)r0 * FEAT + col) =
                    __floats2half2_rn(f0, f1);
                *reinterpret_cast<__half2*>(outh + (size_t)(r0 + 8) * FEAT + col) =
                    __floats2half2_rn(f2, f3);
            }
        }
    } else {
        // -------- layer-3 epilogue: bias + relu + head partials --------
        // slot = by*2 + wn: each warp covers a distinct 64-column half.
        const int slot = by * 2 + wn;
        #pragma unroll
        for (int t = 0; t < 4; t++) {
            const int r0 = m0 + wm * 64 + t * 16 + (lane >> 2);
            float p0a = 0.0f, p1a = 0.0f;   // row r0
            float p0b = 0.0f, p1b = 0.0f;   // row r0 + 8
            #pragma unroll
            for (int n = 0; n < 8; n++) {
                const int col = n0 + wn * 64 + n * 8 + (lane & 3) * 2;
                const float2 bv = *reinterpret_cast<const float2*>(bias + col);
                const float2 w0 = *reinterpret_cast<const float2*>(Wh + col);
                const float2 w1 = *reinterpret_cast<const float2*>(Wh + FEAT + col);
                float f0 = fmaxf(acc[t][n][0] + bv.x, 0.0f);
                float f1 = fmaxf(acc[t][n][1] + bv.y, 0.0f);
                float f2 = fmaxf(acc[t][n][2] + bv.x, 0.0f);
                float f3 = fmaxf(acc[t][n][3] + bv.y, 0.0f);
                p0a += f0 * w0.x + f1 * w0.y;
                p1a += f0 * w1.x + f1 * w1.y;
                p0b += f2 * w0.x + f3 * w0.y;
                p1b += f2 * w1.x + f3 * w1.y;
            }
            // quad reduce (lanes sharing lane>>2 hold same rows)
            #pragma unroll
            for (int off = 1; off < 4; off <<= 1) {
                p0a += __shfl_xor_sync(0xFFFFFFFFu, p0a, off);
                p1a += __shfl_xor_sync(0xFFFFFFFFu, p1a, off);
                p0b += __shfl_xor_sync(0xFFFFFFFFu, p0b, off);
                p1b += __shfl_xor_sync(0xFFFFFFFFu, p1b, off);
            }
            if ((lane & 3) == 0) {
                g_part[(size_t)r0 * 32 + slot]       = make_float2(p0a, p1a);
                g_part[(size_t)(r0 + 8) * 32 + slot] = make_float2(p0b, p1b);
            }
        }
    }
    __threadfence();
    __syncthreads();
    if (tid == 0) atomicAdd(&g_gdone[layer][bx], 1);
}

// ---------------------------------------------------------------------------
// Prep: zero scheduler state; sigmoid(x*s+c)->fp16; convert W0 fp32->fp16
// ---------------------------------------------------------------------------
#define SIG_N4 ((BATCH * FEAT) / 4)
#define CVT_N4 ((FEAT * FEAT) / 4)

__global__ void prep_kernel(const float* __restrict__ x,
                            const float* __restrict__ cw,
                            const float* __restrict__ cb,
                            __half* __restrict__ o,
                            const float* __restrict__ W0)
{
    if (blockIdx.x == 0 && threadIdx.x == 0) {
        for (int l = 0; l < 4; l++)
            for (int b = 0; b < 32; b++) g_gdone[l][b] = 0;
        for (int g = 0; g < 3; g++) g_cdone[g] = 0;
    }
    const int gsz = gridDim.x * blockDim.x;
    int g = blockIdx.x * blockDim.x + threadIdx.x;
    const float s = cw[0] + cw[1] + cw[2] + cw[3];
    const float c = cb[0];
    const float4* x4 = (const float4*)x;
    uint2* o4 = (uint2*)o;
    const int total = SIG_N4 + CVT_N4;
    for (; g < total; g += gsz) {
        if (g < SIG_N4) {
            float4 v = x4[g];
            float a0 = 1.0f / (1.0f + __expf(-(v.x * s + c)));
            float a1 = 1.0f / (1.0f + __expf(-(v.y * s + c)));
            float a2 = 1.0f / (1.0f + __expf(-(v.z * s + c)));
            float a3 = 1.0f / (1.0f + __expf(-(v.w * s + c)));
            __half2 h0 = __floats2half2_rn(a0, a1);
            __half2 h1 = __floats2half2_rn(a2, a3);
            o4[g] = make_uint2(*reinterpret_cast<uint32_t*>(&h0),
                               *reinterpret_cast<uint32_t*>(&h1));
        } else {
            int w = g - SIG_N4;
            float4 v = ((const float4*)W0)[w];
            __half2 h0 = __floats2half2_rn(v.x, v.y);
            __half2 h1 = __floats2half2_rn(v.z, v.w);
            ((uint2*)g_w[0])[w] = make_uint2(*reinterpret_cast<uint32_t*>(&h0),
                                             *reinterpret_cast<uint32_t*>(&h1));
        }
    }
}

// ---------------------------------------------------------------------------
// Launch
// ---------------------------------------------------------------------------
extern "C" void kernel_launch(void* const* d_in, const int* in_sizes, int n_in,
                              void* d_out, int out_size)
{
    const float* x  = (const float*)d_in[0];
    const float* cw = (const float*)d_in[1];
    const float* cb = (const float*)d_in[2];
    const float* Ws[4] = {(const float*)d_in[3], (const float*)d_in[5],
                          (const float*)d_in[7], (const float*)d_in[9]};
    const float* bs[4] = {(const float*)d_in[4], (const float*)d_in[6],
                          (const float*)d_in[8], (const float*)d_in[10]};
    const float* Wh = (const float*)d_in[11];
    const float* bh = (const float*)d_in[12];
    float* out = (float*)d_out;

    __half* act = nullptr;
    cudaGetSymbolAddress((void**)&act, g_act);

    cudaFuncSetAttribute(fused_net_kernel,
                         cudaFuncAttributeMaxDynamicSharedMemorySize, SMEM_BYTES);

    prep_kernel<<<1184, 256>>>(x, cw, cb, act, Ws[0]);
    fused_net_kernel<<<TOTALT, 128, SMEM_BYTES>>>(
        bs[0], bs[1], bs[2], bs[3], Ws[1], Ws[2], Ws[3], Wh, bh, out);
}

// round 15
// speedup vs baseline: 1.3423x; 1.0437x over previous
#include <cuda_runtime.h>
#include <cuda_fp16.h>
#include <cstdint>
#include <cstddef>

// ---------------------------------------------------------------------------
// Problem dims
// ---------------------------------------------------------------------------
#define BATCH 4096
#define FEAT  2048

// GEMM tiling: CTA 128x128, 4 warps of 64x64, BK=64, 3-stage pipeline
#define BM 128
#define BN 128
#define BK 64
#define NCHUNK (FEAT / BK)     // 32
#define STG 3

// Merged-grid tile layout (topological bid order):
//  layers 0-2: blocks of 576. positions 0..127 alternate GEMM g=0..63 (even)
//              with the 64 cvt tiles for W(layer+1) (odd) — cvt completes
//              ~25% into the block so the NEXT layer can pipeline on gdone.
//              positions 128..575 are GEMM g=64..511 (bx-major).
//  layer 3:    512 GEMM tiles (epilogue emits head partials, no h store).
//  reduce:     32 tiles (one per bx) summing head partials.  total 2272.
#define LBLK   576
#define T_L3   (3 * LBLK)              // 1728
#define T_RED  (T_L3 + 512)            // 2240
#define TOTALT (T_RED + 32)            // 2272

// Shared memory: row = 64 halfs = 128B = 8 x 16B units.
#define ASTG (BM * 128)                // 16384 B per stage
#define BSTG (BN * 128)                // 16384 B per stage
#define SM_A 0
#define SM_B (STG * ASTG)              // 49152
#define SMEM_BYTES (SM_B + STG * BSTG) // 98304

// ---------------------------------------------------------------------------
// Device scratch + scheduling state (allocation-free rule: __device__ globals)
// ---------------------------------------------------------------------------
__device__ __align__(16) __half g_w[4][(size_t)FEAT * FEAT];     // 64 MB fp16 weights
__device__ __align__(16) __half g_act[2][(size_t)BATCH * FEAT];  // 32 MB activations
// head partials: 32 slots per row = (by, wn) pairs; 1 MB
__device__ __align__(16) float2 g_part[(size_t)BATCH * 32];
__device__ int g_gdone[4][32];   // per (layer, bx) completed column-tiles (target 16)
__device__ int g_cdone[3];       // per converted weight (target 64)

// ---------------------------------------------------------------------------
// PTX helpers (plain compute_80-level PTX: legal on compute_103)
// ---------------------------------------------------------------------------
__device__ __forceinline__ uint32_t smem_u32(const void* p) {
    uint32_t a;
    asm("{ .reg .u64 t; cvta.to.shared.u64 t, %1; cvt.u32.u64 %0, t; }"
        : "=r"(a) : "l"(p));
    return a;
}

__device__ __forceinline__ void cp_async16(uint32_t dst, const void* src) {
    asm volatile("cp.async.cg.shared.global [%0], [%1], 16;"
                 :: "r"(dst), "l"(src));
}
#define CP_COMMIT() asm volatile("cp.async.commit_group;" ::: "memory")
#define CP_WAIT(n)  asm volatile("cp.async.wait_group %0;" :: "n"(n) : "memory")

__device__ __forceinline__ void ldm_x4(uint32_t* r, uint32_t addr) {
    asm volatile("ldmatrix.sync.aligned.m8n8.x4.shared.b16 {%0,%1,%2,%3}, [%4];"
                 : "=r"(r[0]), "=r"(r[1]), "=r"(r[2]), "=r"(r[3]) : "r"(addr));
}

__device__ __forceinline__ void mma16816(float* c, const uint32_t* a, const uint32_t* b) {
    asm volatile(
        "mma.sync.aligned.m16n8k16.row.col.f32.f16.f16.f32 "
        "{%0,%1,%2,%3}, {%4,%5,%6,%7}, {%8,%9}, {%0,%1,%2,%3};"
        : "+f"(c[0]), "+f"(c[1]), "+f"(c[2]), "+f"(c[3])
        : "r"(a[0]), "r"(a[1]), "r"(a[2]), "r"(a[3]), "r"(b[0]), "r"(b[1]));
}

// L2-coherent vector load (L1 bypass) for data written earlier in this kernel
__device__ __forceinline__ uint4 ldg_cg_v4(const void* p) {
    uint4 v;
    asm volatile("ld.global.cg.v4.u32 {%0,%1,%2,%3}, [%4];"
                 : "=r"(v.x), "=r"(v.y), "=r"(v.z), "=r"(v.w) : "l"(p));
    return v;
}

// Swizzle for 128B rows (8 x 16B units): phys unit = u ^ (row & 7).
__device__ __forceinline__ uint32_t sw_off(int row, int u) {
    return (uint32_t)(row * 128 + ((u ^ (row & 7)) << 4));
}

// ---------------------------------------------------------------------------
// Merged network kernel: one tile per CTA, HW-scheduled, dep-gated by counters
// ---------------------------------------------------------------------------
__global__ void __launch_bounds__(128, 2)
fused_net_kernel(const float* __restrict__ b0, const float* __restrict__ b1,
                 const float* __restrict__ b2, const float* __restrict__ b3,
                 const float* __restrict__ W1f, const float* __restrict__ W2f,
                 const float* __restrict__ W3f,
                 const float* __restrict__ Wh, const float* __restrict__ bh,
                 float* __restrict__ outp)
{
    extern __shared__ char smem[];
    const uint32_t sb = smem_u32(smem);

    const int tid  = threadIdx.x;
    const int lane = tid & 31;
    const int wid  = tid >> 5;
    const int id   = blockIdx.x;

    // -------- decode tile --------
    int layer, g = -1, cvt = -1;
    if (id < T_L3) {
        layer = id / LBLK;
        const int pos = id - layer * LBLK;
        if (pos < 128) {
            if (pos & 1) cvt = pos >> 1;    // 64 cvt tiles, early in block
            else         g   = pos >> 1;    // GEMM g = 0..63
        } else {
            g = pos - 64;                   // GEMM g = 64..511
        }
    } else if (id < T_RED) {
        layer = 3;
        g = id - T_L3;
    } else {
        layer = 4;                          // head reduce
    }

    if (cvt >= 0) {
        // ================= weight converter tile =================
        const float* src = (layer == 0) ? W1f : (layer == 1) ? W2f : W3f;
        const int per = (FEAT * FEAT / 4) / 64;            // 16384 float4
        const float4* s4 = (const float4*)src + (size_t)cvt * per;
        uint2* d4 = (uint2*)g_w[layer + 1] + (size_t)cvt * per;
        #pragma unroll 4
        for (int i = tid; i < per; i += 128) {
            float4 v = s4[i];
            __half2 h0 = __floats2half2_rn(v.x, v.y);
            __half2 h1 = __floats2half2_rn(v.z, v.w);
            d4[i] = make_uint2(*reinterpret_cast<uint32_t*>(&h0),
                               *reinterpret_cast<uint32_t*>(&h1));
        }
        __threadfence();
        __syncthreads();
        if (tid == 0) atomicAdd(&g_cdone[layer], 1);
        return;
    }

    if (layer == 4) {
        // ================= head reduce tile: 128 rows, fixed slot order =====
        const int bx = id - T_RED;                  // 0..31
        if (tid == 0)
            while (*(volatile int*)&g_gdone[3][bx] < 16) __nanosleep(64);
        __syncthreads();

        const int row = bx * 128 + tid;
        const char* base = (const char*)&g_part[(size_t)row * 32];  // 256B
        float s0 = bh[0], s1 = bh[1];
        #pragma unroll
        for (int q = 0; q < 16; q++) {              // 16 x 16B = 32 float2
            uint4 v = ldg_cg_v4(base + q * 16);
            s0 += __uint_as_float(v.x) + __uint_as_float(v.z);
            s1 += __uint_as_float(v.y) + __uint_as_float(v.w);
        }
        outp[row * 2 + 0] = s0;
        outp[row * 2 + 1] = s1;
        return;
    }

    // ================= GEMM tile =================
    const int bx = g >> 4, by = g & 15;             // bx-major ordering
    const int m0 = bx * BM, n0 = by * BN;

    if (tid == 0 && layer > 0) {
        while (*(volatile int*)&g_gdone[layer - 1][bx] < 16) __nanosleep(64);
        while (*(volatile int*)&g_cdone[layer - 1] < 64) __nanosleep(64);
    }
    __syncthreads();

    const __half* A = g_act[layer & 1];
    const __half* W = g_w[layer];
    const float* bias = (layer == 0) ? b0 : (layer == 1) ? b1
                      : (layer == 2) ? b2 : b3;
    __half* outh = g_act[(layer + 1) & 1];

    const int wm = wid >> 1, wn = wid & 1;
    const int grp = lane >> 3;
    uint32_t pa[4], qa[4];
    #pragma unroll
    for (int t = 0; t < 4; t++) {
        int row = wm * 64 + t * 16 + (grp & 1) * 8 + (lane & 7);
        pa[t] = (uint32_t)(row * 128);
        qa[t] = (uint32_t)((grp >> 1) ^ (row & 7));
    }
    uint32_t pb[4], qb[4];
    #pragma unroll
    for (int p = 0; p < 4; p++) {
        int row = wn * 64 + p * 16 + (grp >> 1) * 8 + (lane & 7);
        pb[p] = (uint32_t)(row * 128);
        qb[p] = (uint32_t)((grp & 1) ^ (row & 7));
    }
    const int lrow = tid >> 3, lu = tid & 7;
    const __half* agp = A + (size_t)(m0 + lrow) * FEAT + lu * 8;
    const __half* bgp = W + (size_t)(n0 + lrow) * FEAT + lu * 8;

    auto load_chunk = [&](int ck, int s) {
        const int k0 = ck * BK;
        #pragma unroll
        for (int i = 0; i < 8; i++) {
            int row = lrow + i * 16;
            cp_async16(sb + SM_A + s * ASTG + sw_off(row, lu),
                       agp + (size_t)i * 16 * FEAT + k0);
        }
        #pragma unroll
        for (int i = 0; i < 8; i++) {
            int row = lrow + i * 16;
            cp_async16(sb + SM_B + s * BSTG + sw_off(row, lu),
                       bgp + (size_t)i * 16 * FEAT + k0);
        }
        CP_COMMIT();
    };

    uint32_t af[2][4][4], bf[2][8][2];
    auto preload = [&](int buf, uint32_t ab, uint32_t bb, uint32_t ux) {
        #pragma unroll
        for (int t = 0; t < 4; t++)
            ldm_x4(af[buf][t], ab + pa[t] + ((qa[t] ^ ux) << 4));
        #pragma unroll
        for (int p = 0; p < 4; p++) {
            uint32_t r[4];
            ldm_x4(r, bb + pb[p] + ((qb[p] ^ ux) << 4));
            bf[buf][2 * p][0] = r[0]; bf[buf][2 * p][1] = r[1];
            bf[buf][2 * p + 1][0] = r[2]; bf[buf][2 * p + 1][1] = r[3];
        }
    };

    float acc[4][8][4];
    #pragma unroll
    for (int t = 0; t < 4; t++)
        #pragma unroll
        for (int n = 0; n < 8; n++)
            #pragma unroll
            for (int e = 0; e < 4; e++) acc[t][n][e] = 0.0f;

    load_chunk(0, 0);
    load_chunk(1, 1);
    CP_WAIT(1);
    __syncthreads();
    preload(0, sb + SM_A, sb + SM_B, 0);

    int s = 0;
    for (int i = 0; i < NCHUNK; i++) {
        const uint32_t ab = sb + SM_A + s * ASTG;
        const uint32_t bb = sb + SM_B + s * BSTG;

        if (i + 2 < NCHUNK) {
            int ls = s + 2; if (ls >= STG) ls -= STG;
            load_chunk(i + 2, ls);
        }

        #pragma unroll
        for (int ks = 0; ks < 3; ks++) {
            const int cur = ks & 1;
            preload(cur ^ 1, ab, bb, (uint32_t)(2 * (ks + 1)));
            #pragma unroll
            for (int t = 0; t < 4; t++)
                #pragma unroll
                for (int n = 0; n < 8; n++)
                    mma16816(acc[t][n], af[cur][t], bf[cur][n]);
        }

        if (i + 1 < NCHUNK) {
            if (i + 2 < NCHUNK) CP_WAIT(1); else CP_WAIT(0);
            __syncthreads();
            int ns = s + 1; if (ns >= STG) ns -= STG;
            preload(0, sb + SM_A + ns * ASTG, sb + SM_B + ns * BSTG, 0);
        }
        #pragma unroll
        for (int t = 0; t < 4; t++)
            #pragma unroll
            for (int n = 0; n < 8; n++)
                mma16816(acc[t][n], af[1][t], bf[1][n]);

        if (++s == STG) s = 0;
    }

    if (layer < 3) {
        // -------- epilogue: bias + relu + fp16 store --------
        #pragma unroll
        for (int t = 0; t < 4; t++) {
            const int r0 = m0 + wm * 64 + t * 16 + (lane >> 2);
            #pragma unroll
            for (int n = 0; n < 8; n++) {
                const int col = n0 + wn * 64 + n * 8 + (lane & 3) * 2;
                const float2 bv = *reinterpret_cast<const float2*>(bias + col);
                float f0 = fmaxf(acc[t][n][0] + bv.x, 0.0f);
                float f1 = fmaxf(acc[t][n][1] + bv.y, 0.0f);
                float f2 = fmaxf(acc[t][n][2] + bv.x, 0.0f);
                float f3 = fmaxf(acc[t][n][3] + bv.y, 0.0f);
                *reinterpret_cast<__half2*>(outh + (size_t)r0 * FEAT + col) =
                    __floats2half2_rn(f0, f1);
                *reinterpret_cast<__half2*>(outh + (size_t)(r0 + 8) * FEAT + col) =
                    __floats2half2_rn(f2, f3);
            }
        }
    } else {
        // -------- layer-3 epilogue: bias + relu + head partials --------
        // slot = by*2 + wn: each warp covers a distinct 64-column half.
        const int slot = by * 2 + wn;
        #pragma unroll
        for (int t = 0; t < 4; t++) {
            const int r0 = m0 + wm * 64 + t * 16 + (lane >> 2);
            float p0a = 0.0f, p1a = 0.0f;   // row r0
            float p0b = 0.0f, p1b = 0.0f;   // row r0 + 8
            #pragma unroll
            for (int n = 0; n < 8; n++) {
                const int col = n0 + wn * 64 + n * 8 + (lane & 3) * 2;
                const float2 bv = *reinterpret_cast<const float2*>(bias + col);
                const float2 w0 = *reinterpret_cast<const float2*>(Wh + col);
                const float2 w1 = *reinterpret_cast<const float2*>(Wh + FEAT + col);
                float f0 = fmaxf(acc[t][n][0] + bv.x, 0.0f);
                float f1 = fmaxf(acc[t][n][1] + bv.y, 0.0f);
                float f2 = fmaxf(acc[t][n][2] + bv.x, 0.0f);
                float f3 = fmaxf(acc[t][n][3] + bv.y, 0.0f);
                p0a += f0 * w0.x + f1 * w0.y;
                p1a += f0 * w1.x + f1 * w1.y;
                p0b += f2 * w0.x + f3 * w0.y;
                p1b += f2 * w1.x + f3 * w1.y;
            }
            // quad reduce (lanes sharing lane>>2 hold same rows)
            #pragma unroll
            for (int off = 1; off < 4; off <<= 1) {
                p0a += __shfl_xor_sync(0xFFFFFFFFu, p0a, off);
                p1a += __shfl_xor_sync(0xFFFFFFFFu, p1a, off);
                p0b += __shfl_xor_sync(0xFFFFFFFFu, p0b, off);
                p1b += __shfl_xor_sync(0xFFFFFFFFu, p1b, off);
            }
            if ((lane & 3) == 0) {
                g_part[(size_t)r0 * 32 + slot]       = make_float2(p0a, p1a);
                g_part[(size_t)(r0 + 8) * 32 + slot] = make_float2(p0b, p1b);
            }
        }
    }
    __threadfence();
    __syncthreads();
    if (tid == 0) atomicAdd(&g_gdone[layer][bx], 1);
}

// ---------------------------------------------------------------------------
// Prep: zero scheduler state; sigmoid(x*s+c)->fp16; convert W0 fp32->fp16
// ---------------------------------------------------------------------------
#define SIG_N4 ((BATCH * FEAT) / 4)
#define CVT_N4 ((FEAT * FEAT) / 4)

__global__ void prep_kernel(const float* __restrict__ x,
                            const float* __restrict__ cw,
                            const float* __restrict__ cb,
                            __half* __restrict__ o,
                            const float* __restrict__ W0)
{
    if (blockIdx.x == 0 && threadIdx.x == 0) {
        for (int l = 0; l < 4; l++)
            for (int b = 0; b < 32; b++) g_gdone[l][b] = 0;
        for (int g = 0; g < 3; g++) g_cdone[g] = 0;
    }
    const int gsz = gridDim.x * blockDim.x;
    int g = blockIdx.x * blockDim.x + threadIdx.x;
    const float s = cw[0] + cw[1] + cw[2] + cw[3];
    const float c = cb[0];
    const float4* x4 = (const float4*)x;
    uint2* o4 = (uint2*)o;
    const int total = SIG_N4 + CVT_N4;
    for (; g < total; g += gsz) {
        if (g < SIG_N4) {
            float4 v = x4[g];
            float a0 = 1.0f / (1.0f + __expf(-(v.x * s + c)));
            float a1 = 1.0f / (1.0f + __expf(-(v.y * s + c)));
            float a2 = 1.0f / (1.0f + __expf(-(v.z * s + c)));
            float a3 = 1.0f / (1.0f + __expf(-(v.w * s + c)));
            __half2 h0 = __floats2half2_rn(a0, a1);
            __half2 h1 = __floats2half2_rn(a2, a3);
            o4[g] = make_uint2(*reinterpret_cast<uint32_t*>(&h0),
                               *reinterpret_cast<uint32_t*>(&h1));
        } else {
            int w = g - SIG_N4;
            float4 v = ((const float4*)W0)[w];
            __half2 h0 = __floats2half2_rn(v.x, v.y);
            __half2 h1 = __floats2half2_rn(v.z, v.w);
            ((uint2*)g_w[0])[w] = make_uint2(*reinterpret_cast<uint32_t*>(&h0),
                                             *reinterpret_cast<uint32_t*>(&h1));
        }
    }
}

// ---------------------------------------------------------------------------
// Launch
// ---------------------------------------------------------------------------
extern "C" void kernel_launch(void* const* d_in, const int* in_sizes, int n_in,
                              void* d_out, int out_size)
{
    const float* x  = (const float*)d_in[0];
    const float* cw = (const float*)d_in[1];
    const float* cb = (const float*)d_in[2];
    const float* Ws[4] = {(const float*)d_in[3], (const float*)d_in[5],
                          (const float*)d_in[7], (const float*)d_in[9]};
    const float* bs[4] = {(const float*)d_in[4], (const float*)d_in[6],
                          (const float*)d_in[8], (const float*)d_in[10]};
    const float* Wh = (const float*)d_in[11];
    const float* bh = (const float*)d_in[12];
    float* out = (float*)d_out;

    __half* act = nullptr;
    cudaGetSymbolAddress((void**)&act, g_act);

    cudaFuncSetAttribute(fused_net_kernel,
                         cudaFuncAttributeMaxDynamicSharedMemorySize, SMEM_BYTES);

    prep_kernel<<<1184, 256>>>(x, cw, cb, act, Ws[0]);
    fused_net_kernel<<<TOTALT, 128, SMEM_BYTES>>>(
        bs[0], bs[1], bs[2], bs[3], Ws[1], Ws[2], Ws[3], Wh, bh, out);
}